// round 10
// baseline (speedup 1.0000x reference)
#include <cuda_runtime.h>

// Problem constants (from reference setup_inputs)
#define NB 8
#define NC 64
#define HH 128
#define WW 128
#define EH 64
#define EW 64
#define THETA 10.0f

#define CSPB 8                         // channels per block (apply kernel)
#define NCGRP (NC / CSPB)              // 8 channel groups
#define ROWS_PER_BLK 4                 // 4 warps -> 4 rows
#define NROWBLK (HH / ROWS_PER_BLK)    // 32
#define TBLK (ROWS_PER_BLK * 32)       // 128 threads
#define NSTAGE 4                       // cp.async ring depth (3 ahead)

// Precomputed normalized weights: [n][y][k][x], k = 0..8 tap index.
// 8*128*9*128 floats = 4.72 MB (static device scratch; no runtime alloc).
__device__ float g_wbuf[NB * HH * 9 * WW];

#define CP16(dst, src) \
    asm volatile("cp.async.cg.shared.global [%0], [%1], 16;" \
                 :: "r"(dst), "l"(src) : "memory")
#define CPCOMMIT() asm volatile("cp.async.commit_group;" ::: "memory")
#define CPWAIT3()  asm volatile("cp.async.wait_group 3;"  ::: "memory")

// ---------------------------------------------------------------------------
// Kernel 1: per-pixel softmax weights from bilinear-upsampled edge.
// Boundary zero-padding of the MASK taps is folded into the stored weights
// (padded tap contributes m=0, identical to zero weight; softmax denominator
// already includes all 9 exps).
// ---------------------------------------------------------------------------
__global__ __launch_bounds__(TBLK)
void geg_weights_kernel(const float* __restrict__ edge)
{
    const int t    = threadIdx.x;
    const int warp = t >> 5;
    const int lane = t & 31;
    const int y    = blockIdx.x * ROWS_PER_BLK + warp;  // 0..127
    const int n    = blockIdx.y;                        // 0..7
    const int x0   = lane * 4;

    const float* eptr = edge + n * (EH * EW);
    const float sc = 63.0f / 127.0f;   // (EH-1)/(HH-1), align_corners

    float er[3][6];
    #pragma unroll
    for (int r = 0; r < 3; r++) {
        const int gy = y - 1 + r;
        float4 ev = make_float4(0.f, 0.f, 0.f, 0.f);
        if (gy >= 0 && gy < HH) {
            const float ys = (float)gy * sc;
            const int   yi = (int)ys;
            const float wy = ys - (float)yi;
            const int   y1 = min(yi + 1, EH - 1);
            const float* r0 = eptr + yi * EW;
            const float* r1 = eptr + y1 * EW;
            float v[4];
            #pragma unroll
            for (int p = 0; p < 4; p++) {
                const int   gx = x0 + p;
                const float xs = (float)gx * sc;
                const int   xi = (int)xs;
                const float wx = xs - (float)xi;
                const int   x1 = min(xi + 1, EW - 1);
                const float a  = r0[xi];
                const float b  = r0[x1];
                const float c0 = r1[xi];
                const float d  = r1[x1];
                const float top = a  + (b  - a ) * wx;
                const float bot = c0 + (d  - c0) * wx;
                v[p] = top + (bot - top) * wy;
            }
            ev = make_float4(v[0], v[1], v[2], v[3]);
        }
        float left  = __shfl_up_sync(0xffffffffu, ev.w, 1);
        float right = __shfl_down_sync(0xffffffffu, ev.x, 1);
        if (lane == 0)  left  = 0.f;
        if (lane == 31) right = 0.f;
        er[r][0] = left; er[r][1] = ev.x; er[r][2] = ev.y;
        er[r][3] = ev.z; er[r][4] = ev.w; er[r][5] = right;
    }

    float w[4][9];
    #pragma unroll
    for (int p = 0; p < 4; p++) {
        const float ec = er[1][p + 1];
        float s = 0.f;
        #pragma unroll
        for (int k = 0; k < 9; k++) {
            const float d  = ec - er[k / 3][p + (k % 3)];
            const float pw = __expf(-THETA * d * d);
            w[p][k] = pw;
            s += pw;
        }
        const float rs = 1.f / s;
        #pragma unroll
        for (int k = 0; k < 9; k++) w[p][k] *= rs;
    }

    if (y == 0) {
        #pragma unroll
        for (int p = 0; p < 4; p++) { w[p][0] = 0.f; w[p][1] = 0.f; w[p][2] = 0.f; }
    }
    if (y == HH - 1) {
        #pragma unroll
        for (int p = 0; p < 4; p++) { w[p][6] = 0.f; w[p][7] = 0.f; w[p][8] = 0.f; }
    }
    if (lane == 0)  { w[0][0] = 0.f; w[0][3] = 0.f; w[0][6] = 0.f; }
    if (lane == 31) { w[3][2] = 0.f; w[3][5] = 0.f; w[3][8] = 0.f; }

    float* wb = g_wbuf + (n * HH + y) * (9 * WW) + x0;
    #pragma unroll
    for (int k = 0; k < 9; k++)
        *reinterpret_cast<float4*>(wb + k * WW) =
            make_float4(w[0][k], w[1][k], w[2][k], w[3][k]);
}

// ---------------------------------------------------------------------------
// Kernel 2: apply weights across channels. Warp-private cp.async pipeline:
// each warp stages its 3 mask rows per channel into its own smem ring slot,
// 3 channels ahead, via cp.async.cg (L1 bypass). commit/wait_group are
// per-warp, so there are NO block barriers. Registers stay low (no in-flight
// data registers), smem 24KB/block -> 8 blocks/SM.
// ---------------------------------------------------------------------------
__global__ __launch_bounds__(TBLK, 8)
void geg_apply_kernel(const float* __restrict__ mask,
                      float* __restrict__ out)
{
    // [warp][stage][row][lane] float4
    __shared__ float4 sbuf[ROWS_PER_BLK][NSTAGE][3][32];

    const int t    = threadIdx.x;
    const int warp = t >> 5;
    const int lane = t & 31;

    const int rowblk = blockIdx.x;     // 0..31
    const int cgrp   = blockIdx.y;     // 0..7
    const int n      = blockIdx.z;     // 0..7

    const int y  = rowblk * ROWS_PER_BLK + warp;
    const int x0 = lane * 4;

    const int img  = HH * WW;
    const int base = (n * NC + cgrp * CSPB) * img;
    const float* mp = mask + base;
    float*       op = out  + base;

    // Clamped row offsets (OOB rows carry zero weight).
    const int off0 = max(y - 1, 0)      * WW + x0;
    const int off1 = y                  * WW + x0;
    const int off2 = min(y + 1, HH - 1) * WW + x0;
    const int offs = y * WW + x0;

    const unsigned sbase =
        (unsigned)__cvta_generic_to_shared(&sbuf[warp][0][0][lane]);
    // stage stride = 3 rows * 32 lanes * 16B = 1536B; row stride = 512B

    // Issue stage for channel ch (one commit group = 3 x 16B cp.async).
    // Prologue: channels 0..2 in flight.
    {
        const float* p0 = mp;
        CP16(sbase,        p0 + off0);
        CP16(sbase + 512,  p0 + off1);
        CP16(sbase + 1024, p0 + off2);
        CPCOMMIT();
        const float* p1 = mp + img;
        CP16(sbase + 1536,        p1 + off0);
        CP16(sbase + 1536 + 512,  p1 + off1);
        CP16(sbase + 1536 + 1024, p1 + off2);
        CPCOMMIT();
        const float* p2 = mp + 2 * img;
        CP16(sbase + 3072,        p2 + off0);
        CP16(sbase + 3072 + 512,  p2 + off1);
        CP16(sbase + 3072 + 1024, p2 + off2);
        CPCOMMIT();
    }

    // Load the 36 precomputed weights (9 coalesced float4 loads) while the
    // first cp.async groups are in flight.
    float w[4][9];
    {
        const float* wb = g_wbuf + (n * HH + y) * (9 * WW) + x0;
        #pragma unroll
        for (int k = 0; k < 9; k++) {
            float4 v = *reinterpret_cast<const float4*>(wb + k * WW);
            w[0][k] = v.x; w[1][k] = v.y; w[2][k] = v.z; w[3][k] = v.w;
        }
    }

    #pragma unroll 1
    for (int c = 0; c < CSPB; c++) {
        // Issue channel c+3 (empty commit group when out of range keeps the
        // wait_group accounting uniform).
        if (c + 3 < CSPB) {
            const unsigned st = sbase + ((c + 3) & (NSTAGE - 1)) * 1536;
            const float* p = mp + (c + 3) * img;
            CP16(st,        p + off0);
            CP16(st + 512,  p + off1);
            CP16(st + 1024, p + off2);
        }
        CPCOMMIT();
        CPWAIT3();          // channel c's group is complete

        const float4* st = &sbuf[warp][c & (NSTAGE - 1)][0][lane];
        float4 m0 = st[0];
        float4 m1 = st[32];
        float4 m2 = st[64];

        float mr[3][6];
        {
            float l0 = __shfl_up_sync(0xffffffffu, m0.w, 1);
            float r0 = __shfl_down_sync(0xffffffffu, m0.x, 1);
            float l1 = __shfl_up_sync(0xffffffffu, m1.w, 1);
            float r1 = __shfl_down_sync(0xffffffffu, m1.x, 1);
            float l2 = __shfl_up_sync(0xffffffffu, m2.w, 1);
            float r2 = __shfl_down_sync(0xffffffffu, m2.x, 1);
            mr[0][0]=l0; mr[0][1]=m0.x; mr[0][2]=m0.y; mr[0][3]=m0.z; mr[0][4]=m0.w; mr[0][5]=r0;
            mr[1][0]=l1; mr[1][1]=m1.x; mr[1][2]=m1.y; mr[1][3]=m1.z; mr[1][4]=m1.w; mr[1][5]=r1;
            mr[2][0]=l2; mr[2][1]=m2.x; mr[2][2]=m2.y; mr[2][3]=m2.z; mr[2][4]=m2.w; mr[2][5]=r2;
        }

        float a[4];
        #pragma unroll
        for (int p = 0; p < 4; p++) {
            float s = 0.f;
            #pragma unroll
            for (int k = 0; k < 9; k++)
                s = fmaf(w[p][k], mr[k / 3][p + (k % 3)], s);
            a[p] = s;
        }

        *reinterpret_cast<float4*>(op + offs) = make_float4(a[0], a[1], a[2], a[3]);
        op += img;
    }
}

extern "C" void kernel_launch(void* const* d_in, const int* in_sizes, int n_in,
                              void* d_out, int out_size)
{
    const float* mask = (const float*)d_in[0];
    const float* edge = (const float*)d_in[1];
    if (n_in >= 2 && in_sizes[0] < in_sizes[1]) {   // defensive swap by size
        const float* tmp = mask; mask = edge; edge = tmp;
    }
    float* out = (float*)d_out;

    dim3 wgrid(NROWBLK, NB);            // 32 x 8 = 256 blocks
    geg_weights_kernel<<<wgrid, TBLK>>>(edge);

    dim3 agrid(NROWBLK, NCGRP, NB);     // 32 x 8 x 8 = 2048 blocks
    geg_apply_kernel<<<agrid, TBLK>>>(mask, out);
}

// round 11
// speedup vs baseline: 1.0381x; 1.0381x over previous
#include <cuda_runtime.h>

// Problem constants (from reference setup_inputs)
#define NB 8
#define NC 64
#define HH 128
#define WW 128
#define EH 64
#define EW 64
#define THETA 10.0f

#define CSPB 16                        // channels per block (apply kernel)
#define NCGRP (NC / CSPB)              // 4 channel groups
#define ROWS_PER_BLK 4                 // 4 warps -> 4 rows
#define NROWBLK (HH / ROWS_PER_BLK)    // 32
#define TBLK (ROWS_PER_BLK * 32)       // 128 threads
#define NSTAGE 4                       // cp.async ring depth (3 ahead)

// Precomputed normalized weights: [n][y][k][x], k = 0..8 tap index.
// 8*128*9*128 floats = 4.72 MB (static device scratch; no runtime alloc).
__device__ float g_wbuf[NB * HH * 9 * WW];

#define CP16(dst, src) \
    asm volatile("cp.async.cg.shared.global [%0], [%1], 16;" \
                 :: "r"(dst), "l"(src) : "memory")
#define CPCOMMIT() asm volatile("cp.async.commit_group;" ::: "memory")
#define CPWAIT3()  asm volatile("cp.async.wait_group 3;"  ::: "memory")

// ---------------------------------------------------------------------------
// Kernel 1: per-pixel softmax weights from bilinear-upsampled edge.
// Boundary zero-padding of the MASK taps is folded into the stored weights
// (padded tap contributes m=0, identical to zero weight; softmax denominator
// already includes all 9 exps).
// ---------------------------------------------------------------------------
__global__ __launch_bounds__(TBLK)
void geg_weights_kernel(const float* __restrict__ edge)
{
    const int t    = threadIdx.x;
    const int warp = t >> 5;
    const int lane = t & 31;
    const int y    = blockIdx.x * ROWS_PER_BLK + warp;  // 0..127
    const int n    = blockIdx.y;                        // 0..7
    const int x0   = lane * 4;

    const float* eptr = edge + n * (EH * EW);
    const float sc = 63.0f / 127.0f;   // (EH-1)/(HH-1), align_corners

    float er[3][6];
    #pragma unroll
    for (int r = 0; r < 3; r++) {
        const int gy = y - 1 + r;
        float4 ev = make_float4(0.f, 0.f, 0.f, 0.f);
        if (gy >= 0 && gy < HH) {
            const float ys = (float)gy * sc;
            const int   yi = (int)ys;
            const float wy = ys - (float)yi;
            const int   y1 = min(yi + 1, EH - 1);
            const float* r0 = eptr + yi * EW;
            const float* r1 = eptr + y1 * EW;
            float v[4];
            #pragma unroll
            for (int p = 0; p < 4; p++) {
                const int   gx = x0 + p;
                const float xs = (float)gx * sc;
                const int   xi = (int)xs;
                const float wx = xs - (float)xi;
                const int   x1 = min(xi + 1, EW - 1);
                const float a  = r0[xi];
                const float b  = r0[x1];
                const float c0 = r1[xi];
                const float d  = r1[x1];
                const float top = a  + (b  - a ) * wx;
                const float bot = c0 + (d  - c0) * wx;
                v[p] = top + (bot - top) * wy;
            }
            ev = make_float4(v[0], v[1], v[2], v[3]);
        }
        float left  = __shfl_up_sync(0xffffffffu, ev.w, 1);
        float right = __shfl_down_sync(0xffffffffu, ev.x, 1);
        if (lane == 0)  left  = 0.f;
        if (lane == 31) right = 0.f;
        er[r][0] = left; er[r][1] = ev.x; er[r][2] = ev.y;
        er[r][3] = ev.z; er[r][4] = ev.w; er[r][5] = right;
    }

    float w[4][9];
    #pragma unroll
    for (int p = 0; p < 4; p++) {
        const float ec = er[1][p + 1];
        float s = 0.f;
        #pragma unroll
        for (int k = 0; k < 9; k++) {
            const float d  = ec - er[k / 3][p + (k % 3)];
            const float pw = __expf(-THETA * d * d);
            w[p][k] = pw;
            s += pw;
        }
        const float rs = 1.f / s;
        #pragma unroll
        for (int k = 0; k < 9; k++) w[p][k] *= rs;
    }

    if (y == 0) {
        #pragma unroll
        for (int p = 0; p < 4; p++) { w[p][0] = 0.f; w[p][1] = 0.f; w[p][2] = 0.f; }
    }
    if (y == HH - 1) {
        #pragma unroll
        for (int p = 0; p < 4; p++) { w[p][6] = 0.f; w[p][7] = 0.f; w[p][8] = 0.f; }
    }
    if (lane == 0)  { w[0][0] = 0.f; w[0][3] = 0.f; w[0][6] = 0.f; }
    if (lane == 31) { w[3][2] = 0.f; w[3][5] = 0.f; w[3][8] = 0.f; }

    float* wb = g_wbuf + (n * HH + y) * (9 * WW) + x0;
    #pragma unroll
    for (int k = 0; k < 9; k++)
        *reinterpret_cast<float4*>(wb + k * WW) =
            make_float4(w[0][k], w[1][k], w[2][k], w[3][k]);
}

// ---------------------------------------------------------------------------
// Kernel 2: apply weights across channels. Warp-private cp.async pipeline
// (3 channels ahead, per-warp commit/wait, NO block barriers). CSPB=16 ->
// grid 1024 = single wave at 8 blocks/SM cap; prologue amortized 2x vs R10.
// ---------------------------------------------------------------------------
__global__ __launch_bounds__(TBLK, 8)
void geg_apply_kernel(const float* __restrict__ mask,
                      float* __restrict__ out)
{
    // [warp][stage][row][lane] float4 = 24 KB
    __shared__ float4 sbuf[ROWS_PER_BLK][NSTAGE][3][32];

    const int t    = threadIdx.x;
    const int warp = t >> 5;
    const int lane = t & 31;

    const int rowblk = blockIdx.x;     // 0..31
    const int cgrp   = blockIdx.y;     // 0..3
    const int n      = blockIdx.z;     // 0..7

    const int y  = rowblk * ROWS_PER_BLK + warp;
    const int x0 = lane * 4;

    const int img  = HH * WW;
    const int base = (n * NC + cgrp * CSPB) * img;
    const float* mp = mask + base;
    float*       op = out  + base;

    // Clamped row offsets (OOB rows carry zero weight).
    const int off0 = max(y - 1, 0)      * WW + x0;
    const int off1 = y                  * WW + x0;
    const int off2 = min(y + 1, HH - 1) * WW + x0;
    const int offs = y * WW + x0;

    const unsigned sbase =
        (unsigned)__cvta_generic_to_shared(&sbuf[warp][0][0][lane]);
    // stage stride = 3 rows * 32 lanes * 16B = 1536B; row stride = 512B

    // Prologue: channels 0..2 in flight (one commit group per channel).
    {
        const float* p0 = mp;
        CP16(sbase,        p0 + off0);
        CP16(sbase + 512,  p0 + off1);
        CP16(sbase + 1024, p0 + off2);
        CPCOMMIT();
        const float* p1 = mp + img;
        CP16(sbase + 1536,        p1 + off0);
        CP16(sbase + 1536 + 512,  p1 + off1);
        CP16(sbase + 1536 + 1024, p1 + off2);
        CPCOMMIT();
        const float* p2 = mp + 2 * img;
        CP16(sbase + 3072,        p2 + off0);
        CP16(sbase + 3072 + 512,  p2 + off1);
        CP16(sbase + 3072 + 1024, p2 + off2);
        CPCOMMIT();
    }

    // Load the 36 precomputed weights while the first groups are in flight.
    float w[4][9];
    {
        const float* wb = g_wbuf + (n * HH + y) * (9 * WW) + x0;
        #pragma unroll
        for (int k = 0; k < 9; k++) {
            float4 v = *reinterpret_cast<const float4*>(wb + k * WW);
            w[0][k] = v.x; w[1][k] = v.y; w[2][k] = v.z; w[3][k] = v.w;
        }
    }

    #pragma unroll 1
    for (int c = 0; c < CSPB; c++) {
        // Issue channel c+3. Empty commit groups in the tail keep wait_group
        // accounting sound (channel c's group must NOT be among the 3 most
        // recent at the wait below).
        if (c + 3 < CSPB) {
            const unsigned st = sbase + ((c + 3) & (NSTAGE - 1)) * 1536;
            const float* p = mp + (c + 3) * img;
            CP16(st,        p + off0);
            CP16(st + 512,  p + off1);
            CP16(st + 1024, p + off2);
        }
        CPCOMMIT();
        CPWAIT3();          // channel c's group is complete

        const float4* st = &sbuf[warp][c & (NSTAGE - 1)][0][lane];
        float4 m0 = st[0];
        float4 m1 = st[32];
        float4 m2 = st[64];

        float mr[3][6];
        {
            float l0 = __shfl_up_sync(0xffffffffu, m0.w, 1);
            float r0 = __shfl_down_sync(0xffffffffu, m0.x, 1);
            float l1 = __shfl_up_sync(0xffffffffu, m1.w, 1);
            float r1 = __shfl_down_sync(0xffffffffu, m1.x, 1);
            float l2 = __shfl_up_sync(0xffffffffu, m2.w, 1);
            float r2 = __shfl_down_sync(0xffffffffu, m2.x, 1);
            mr[0][0]=l0; mr[0][1]=m0.x; mr[0][2]=m0.y; mr[0][3]=m0.z; mr[0][4]=m0.w; mr[0][5]=r0;
            mr[1][0]=l1; mr[1][1]=m1.x; mr[1][2]=m1.y; mr[1][3]=m1.z; mr[1][4]=m1.w; mr[1][5]=r1;
            mr[2][0]=l2; mr[2][1]=m2.x; mr[2][2]=m2.y; mr[2][3]=m2.z; mr[2][4]=m2.w; mr[2][5]=r2;
        }

        float a[4];
        #pragma unroll
        for (int p = 0; p < 4; p++) {
            float s = 0.f;
            #pragma unroll
            for (int k = 0; k < 9; k++)
                s = fmaf(w[p][k], mr[k / 3][p + (k % 3)], s);
            a[p] = s;
        }

        *reinterpret_cast<float4*>(op + offs) = make_float4(a[0], a[1], a[2], a[3]);
        op += img;
    }
}

extern "C" void kernel_launch(void* const* d_in, const int* in_sizes, int n_in,
                              void* d_out, int out_size)
{
    const float* mask = (const float*)d_in[0];
    const float* edge = (const float*)d_in[1];
    if (n_in >= 2 && in_sizes[0] < in_sizes[1]) {   // defensive swap by size
        const float* tmp = mask; mask = edge; edge = tmp;
    }
    float* out = (float*)d_out;

    dim3 wgrid(NROWBLK, NB);            // 32 x 8 = 256 blocks
    geg_weights_kernel<<<wgrid, TBLK>>>(edge);

    dim3 agrid(NROWBLK, NCGRP, NB);     // 32 x 4 x 8 = 1024 blocks
    geg_apply_kernel<<<agrid, TBLK>>>(mask, out);
}

// round 12
// speedup vs baseline: 1.1385x; 1.0968x over previous
#include <cuda_runtime.h>

// Problem constants (from reference setup_inputs)
#define NB 8
#define NC 64
#define HH 128
#define WW 128
#define EH 64
#define EW 64
#define THETA 10.0f

#define CSPB 16                        // channels per block
#define NCGRP (NC / CSPB)              // 4 channel groups
#define ROWS_PER_BLK 4                 // 4 warps -> 4 rows
#define NROWBLK (HH / ROWS_PER_BLK)    // 32
#define TBLK (ROWS_PER_BLK * 32)       // 128 threads
#define NSTAGE 4                       // cp.async ring depth (3 ahead)

#define CP16(dst, src) \
    asm volatile("cp.async.cg.shared.global [%0], [%1], 16;" \
                 :: "r"(dst), "l"(src) : "memory")
#define CPCOMMIT() asm volatile("cp.async.commit_group;" ::: "memory")
#define CPWAIT3()  asm volatile("cp.async.wait_group 3;"  ::: "memory")

// ---------------------------------------------------------------------------
// Fused kernel: per-block weight computation (bilinear edge upsample +
// softmax, boundary padding folded into weights) followed by a 16-channel
// apply loop fed by a warp-private cp.async pipeline (3 channels ahead,
// per-warp commit/wait, no block barriers). Single launch, no weight buffer.
// The cp.async prologue is issued BEFORE the weight math so the pipeline
// fill hides behind the expf-heavy prologue.
// ---------------------------------------------------------------------------
__global__ __launch_bounds__(TBLK, 6)
void geg_fused_kernel(const float* __restrict__ mask,
                      const float* __restrict__ edge,
                      float* __restrict__ out)
{
    // [warp][stage][row][lane] float4 = 24 KB
    __shared__ float4 sbuf[ROWS_PER_BLK][NSTAGE][3][32];

    const int t    = threadIdx.x;
    const int warp = t >> 5;
    const int lane = t & 31;

    const int rowblk = blockIdx.x;     // 0..31
    const int cgrp   = blockIdx.y;     // 0..3
    const int n      = blockIdx.z;     // 0..7

    const int y  = rowblk * ROWS_PER_BLK + warp;  // output row, 0..127
    const int x0 = lane * 4;

    const int img  = HH * WW;
    const int base = (n * NC + cgrp * CSPB) * img;
    const float* mp = mask + base;
    float*       op = out  + base;

    // Clamped row offsets (OOB rows carry zero weight).
    const int off0 = max(y - 1, 0)      * WW + x0;
    const int off1 = y                  * WW + x0;
    const int off2 = min(y + 1, HH - 1) * WW + x0;
    const int offs = y * WW + x0;

    const unsigned sbase =
        (unsigned)__cvta_generic_to_shared(&sbuf[warp][0][0][lane]);
    // stage stride = 3 rows * 32 lanes * 16B = 1536B; row stride = 512B

    // ---- cp.async prologue: channels 0..2 in flight ----------------------
    {
        const float* p0 = mp;
        CP16(sbase,        p0 + off0);
        CP16(sbase + 512,  p0 + off1);
        CP16(sbase + 1024, p0 + off2);
        CPCOMMIT();
        const float* p1 = mp + img;
        CP16(sbase + 1536,        p1 + off0);
        CP16(sbase + 1536 + 512,  p1 + off1);
        CP16(sbase + 1536 + 1024, p1 + off2);
        CPCOMMIT();
        const float* p2 = mp + 2 * img;
        CP16(sbase + 3072,        p2 + off0);
        CP16(sbase + 3072 + 512,  p2 + off1);
        CP16(sbase + 3072 + 1024, p2 + off2);
        CPCOMMIT();
    }

    // ---- weights: bilinear-upsampled edge + softmax (overlaps fill) ------
    // e_up(y+dy, x0-1 .. x0+4); zero outside image (reference pads AFTER
    // upsampling). Horizontal neighbors via warp shuffle.
    float w[4][9];
    {
        const float* eptr = edge + n * (EH * EW);
        const float sc = 63.0f / 127.0f;   // (EH-1)/(HH-1), align_corners

        float er[3][6];
        #pragma unroll
        for (int r = 0; r < 3; r++) {
            const int gy = y - 1 + r;
            float4 ev = make_float4(0.f, 0.f, 0.f, 0.f);
            if (gy >= 0 && gy < HH) {
                const float ys = (float)gy * sc;
                const int   yi = (int)ys;
                const float wy = ys - (float)yi;
                const int   y1 = min(yi + 1, EH - 1);
                const float* r0 = eptr + yi * EW;
                const float* r1 = eptr + y1 * EW;
                float v[4];
                #pragma unroll
                for (int p = 0; p < 4; p++) {
                    const int   gx = x0 + p;
                    const float xs = (float)gx * sc;
                    const int   xi = (int)xs;
                    const float wx = xs - (float)xi;
                    const int   x1 = min(xi + 1, EW - 1);
                    const float a  = r0[xi];
                    const float b  = r0[x1];
                    const float c0 = r1[xi];
                    const float d  = r1[x1];
                    const float top = a  + (b  - a ) * wx;
                    const float bot = c0 + (d  - c0) * wx;
                    v[p] = top + (bot - top) * wy;
                }
                ev = make_float4(v[0], v[1], v[2], v[3]);
            }
            float left  = __shfl_up_sync(0xffffffffu, ev.w, 1);
            float right = __shfl_down_sync(0xffffffffu, ev.x, 1);
            if (lane == 0)  left  = 0.f;
            if (lane == 31) right = 0.f;
            er[r][0] = left; er[r][1] = ev.x; er[r][2] = ev.y;
            er[r][3] = ev.z; er[r][4] = ev.w; er[r][5] = right;
        }

        #pragma unroll
        for (int p = 0; p < 4; p++) {
            const float ec = er[1][p + 1];
            float s = 0.f;
            #pragma unroll
            for (int k = 0; k < 9; k++) {
                const float d  = ec - er[k / 3][p + (k % 3)];
                const float pw = __expf(-THETA * d * d);
                w[p][k] = pw;
                s += pw;
            }
            const float rs = 1.f / s;
            #pragma unroll
            for (int k = 0; k < 9; k++) w[p][k] *= rs;
        }

        // Fold mask zero-padding into the (normalized) weights: a padded tap
        // contributes m=0, identical to zeroing its weight; the softmax
        // denominator already includes all 9 exps.
        if (y == 0) {
            #pragma unroll
            for (int p = 0; p < 4; p++) { w[p][0] = 0.f; w[p][1] = 0.f; w[p][2] = 0.f; }
        }
        if (y == HH - 1) {
            #pragma unroll
            for (int p = 0; p < 4; p++) { w[p][6] = 0.f; w[p][7] = 0.f; w[p][8] = 0.f; }
        }
        if (lane == 0)  { w[0][0] = 0.f; w[0][3] = 0.f; w[0][6] = 0.f; }
        if (lane == 31) { w[3][2] = 0.f; w[3][5] = 0.f; w[3][8] = 0.f; }
    }

    // ---- channel loop -----------------------------------------------------
    #pragma unroll 1
    for (int c = 0; c < CSPB; c++) {
        // Issue channel c+3. Empty commit groups in the tail keep wait_group
        // accounting sound (channel c's group must NOT be among the 3 most
        // recent at the wait below).
        if (c + 3 < CSPB) {
            const unsigned st = sbase + ((c + 3) & (NSTAGE - 1)) * 1536;
            const float* p = mp + (c + 3) * img;
            CP16(st,        p + off0);
            CP16(st + 512,  p + off1);
            CP16(st + 1024, p + off2);
        }
        CPCOMMIT();
        CPWAIT3();          // channel c's group is complete

        const float4* st = &sbuf[warp][c & (NSTAGE - 1)][0][lane];
        float4 m0 = st[0];
        float4 m1 = st[32];
        float4 m2 = st[64];

        float mr[3][6];
        {
            float l0 = __shfl_up_sync(0xffffffffu, m0.w, 1);
            float r0 = __shfl_down_sync(0xffffffffu, m0.x, 1);
            float l1 = __shfl_up_sync(0xffffffffu, m1.w, 1);
            float r1 = __shfl_down_sync(0xffffffffu, m1.x, 1);
            float l2 = __shfl_up_sync(0xffffffffu, m2.w, 1);
            float r2 = __shfl_down_sync(0xffffffffu, m2.x, 1);
            mr[0][0]=l0; mr[0][1]=m0.x; mr[0][2]=m0.y; mr[0][3]=m0.z; mr[0][4]=m0.w; mr[0][5]=r0;
            mr[1][0]=l1; mr[1][1]=m1.x; mr[1][2]=m1.y; mr[1][3]=m1.z; mr[1][4]=m1.w; mr[1][5]=r1;
            mr[2][0]=l2; mr[2][1]=m2.x; mr[2][2]=m2.y; mr[2][3]=m2.z; mr[2][4]=m2.w; mr[2][5]=r2;
        }

        float a[4];
        #pragma unroll
        for (int p = 0; p < 4; p++) {
            float s = 0.f;
            #pragma unroll
            for (int k = 0; k < 9; k++)
                s = fmaf(w[p][k], mr[k / 3][p + (k % 3)], s);
            a[p] = s;
        }

        *reinterpret_cast<float4*>(op + offs) = make_float4(a[0], a[1], a[2], a[3]);
        op += img;
    }
}

extern "C" void kernel_launch(void* const* d_in, const int* in_sizes, int n_in,
                              void* d_out, int out_size)
{
    const float* mask = (const float*)d_in[0];
    const float* edge = (const float*)d_in[1];
    if (n_in >= 2 && in_sizes[0] < in_sizes[1]) {   // defensive swap by size
        const float* tmp = mask; mask = edge; edge = tmp;
    }
    float* out = (float*)d_out;

    dim3 grid(NROWBLK, NCGRP, NB);      // 32 x 4 x 8 = 1024 blocks
    geg_fused_kernel<<<grid, TBLK>>>(mask, edge, out);
}